// round 1
// baseline (speedup 1.0000x reference)
#include <cuda_runtime.h>

#define B_SZ  2
#define S_LEN 2048
#define E_DIM 256
#define TQ    32          // q rows per attention block
#define KR    288         // k/v rows per tile: TQ + 2*128
#define SST   292         // Ssm row stride (floats)
#define KST   33          // Ks row stride
#define VST   132         // Vs row stride (16B-aligned rows)

// scratch for q,k,v (no cudaMalloc allowed)
__device__ float g_q[B_SZ * S_LEN * E_DIM];
__device__ float g_k[B_SZ * S_LEN * E_DIM];
__device__ float g_v[B_SZ * S_LEN * E_DIM];

// ---------------------------------------------------------------------------
// Kernel 1: C = X @ W^T + b   (M=4096, N=256, K=256), blockIdx.z selects q/k/v
// 128x128 tile, BK=32, 256 threads, 8x8 micro-tile.
// ---------------------------------------------------------------------------
__global__ __launch_bounds__(256) void qkv_kernel(
    const float* __restrict__ x,
    const float* __restrict__ Wq, const float* __restrict__ bq,
    const float* __restrict__ Wk, const float* __restrict__ bk,
    const float* __restrict__ Wv, const float* __restrict__ bv)
{
    const int z = blockIdx.z;
    const float* __restrict__ W    = (z == 0) ? Wq : (z == 1) ? Wk : Wv;
    const float* __restrict__ bias = (z == 0) ? bq : (z == 1) ? bk : bv;
    float* __restrict__ C          = (z == 0) ? g_q : (z == 1) ? g_k : g_v;

    __shared__ float As[32 * 132];   // [k][m], padded stride 132
    __shared__ float Bs[32 * 132];   // [k][n]

    const int m0 = blockIdx.x * 128;
    const int n0 = blockIdx.y * 128;
    const int tid = threadIdx.x;
    const int tx = tid & 15;         // 0..15 -> 8 output cols
    const int ty = tid >> 4;         // 0..15 -> 8 output rows

    float acc[8][8];
    #pragma unroll
    for (int i = 0; i < 8; i++)
        #pragma unroll
        for (int j = 0; j < 8; j++) acc[i][j] = 0.f;

    for (int kc = 0; kc < 256; kc += 32) {
        #pragma unroll
        for (int p = 0; p < 4; p++) {
            int idx4 = tid + p * 256;
            int row  = idx4 >> 3;            // 0..127
            int c4   = (idx4 & 7) * 4;       // 0..28
            float4 va = *(const float4*)&x[(size_t)(m0 + row) * 256 + kc + c4];
            As[(c4 + 0) * 132 + row] = va.x;
            As[(c4 + 1) * 132 + row] = va.y;
            As[(c4 + 2) * 132 + row] = va.z;
            As[(c4 + 3) * 132 + row] = va.w;
            float4 vb = *(const float4*)&W[(size_t)(n0 + row) * 256 + kc + c4];
            Bs[(c4 + 0) * 132 + row] = vb.x;
            Bs[(c4 + 1) * 132 + row] = vb.y;
            Bs[(c4 + 2) * 132 + row] = vb.z;
            Bs[(c4 + 3) * 132 + row] = vb.w;
        }
        __syncthreads();
        #pragma unroll
        for (int kk = 0; kk < 32; kk++) {
            float4 a0 = *(const float4*)&As[kk * 132 + ty * 8];
            float4 a1 = *(const float4*)&As[kk * 132 + ty * 8 + 4];
            float4 b0 = *(const float4*)&Bs[kk * 132 + tx * 8];
            float4 b1 = *(const float4*)&Bs[kk * 132 + tx * 8 + 4];
            float a[8] = {a0.x, a0.y, a0.z, a0.w, a1.x, a1.y, a1.z, a1.w};
            float b[8] = {b0.x, b0.y, b0.z, b0.w, b1.x, b1.y, b1.z, b1.w};
            #pragma unroll
            for (int i = 0; i < 8; i++)
                #pragma unroll
                for (int j = 0; j < 8; j++)
                    acc[i][j] = fmaf(a[i], b[j], acc[i][j]);
        }
        __syncthreads();
    }

    #pragma unroll
    for (int i = 0; i < 8; i++) {
        int row = m0 + ty * 8 + i;
        #pragma unroll
        for (int j = 0; j < 8; j += 4) {
            int col = n0 + tx * 8 + j;
            float4 o;
            o.x = acc[i][j + 0] + bias[col + 0];
            o.y = acc[i][j + 1] + bias[col + 1];
            o.z = acc[i][j + 2] + bias[col + 2];
            o.w = acc[i][j + 3] + bias[col + 3];
            *(float4*)&C[(size_t)row * 256 + col] = o;
        }
    }
}

// ---------------------------------------------------------------------------
// Kernel 2: banded attention. Block = 32 q rows of one batch.
//   Phase 1: S[32][288] = Q[32,256] @ Kpad[288,256]^T  (zero-padded K -> OOB
//            energies are exactly 0, matching reference F.pad semantics)
//   Softmax over window j in [i, i+256]; zero P outside band.
//   Phase 2: O[32][256] = P[32][288] @ Vpad[288,256]
// ---------------------------------------------------------------------------
__global__ __launch_bounds__(256) void attn_kernel(float* __restrict__ out)
{
    extern __shared__ float sm[];
    float* Ssm = sm;                       // TQ * SST = 9344 floats
    float* Qs  = sm + TQ * SST;            // 32*256 = 8192 floats
    float* Ks  = Qs + TQ * E_DIM;          // 288*33 = 9504 floats
    float* Vs  = sm + TQ * SST;            // 288*132 = 38016 (reuses Qs+Ks)

    const int b   = blockIdx.y;
    const int s0  = blockIdx.x * TQ;
    const int tid = threadIdx.x;
    const int ty  = tid >> 5;              // warp id 0..7
    const int tx  = tid & 31;              // lane

    const float* __restrict__ qg = g_q + (size_t)b * S_LEN * E_DIM;
    const float* __restrict__ kg = g_k + (size_t)b * S_LEN * E_DIM;
    const float* __restrict__ vg = g_v + (size_t)b * S_LEN * E_DIM;

    // load Q tile [32][256]
    #pragma unroll
    for (int p = 0; p < 8; p++) {
        int idx4 = tid + p * 256;
        int row  = idx4 >> 6;
        int c4   = (idx4 & 63) * 4;
        *(float4*)&Qs[row * 256 + c4] =
            *(const float4*)&qg[(size_t)(s0 + row) * 256 + c4];
    }

    // Phase 1: energy GEMM. thread -> 4 q rows (ty*4..) x 9 cols (tx*9..)
    float acc[4][9];
    #pragma unroll
    for (int r = 0; r < 4; r++)
        #pragma unroll
        for (int j = 0; j < 9; j++) acc[r][j] = 0.f;

    for (int kc = 0; kc < 256; kc += 32) {
        __syncthreads();   // Qs ready (1st iter) / prev compute done with Ks
        #pragma unroll
        for (int p = 0; p < 9; p++) {
            int idx4 = tid + p * 256;
            int row  = idx4 >> 3;          // 0..287
            int c4   = (idx4 & 7) * 4;
            int g    = s0 - 128 + row;
            float4 v = make_float4(0.f, 0.f, 0.f, 0.f);
            if ((unsigned)g < S_LEN)
                v = *(const float4*)&kg[(size_t)g * 256 + kc + c4];
            Ks[row * KST + c4 + 0] = v.x;
            Ks[row * KST + c4 + 1] = v.y;
            Ks[row * KST + c4 + 2] = v.z;
            Ks[row * KST + c4 + 3] = v.w;
        }
        __syncthreads();
        #pragma unroll
        for (int kk = 0; kk < 32; kk++) {
            float a0 = Qs[(ty * 4 + 0) * 256 + kc + kk];
            float a1 = Qs[(ty * 4 + 1) * 256 + kc + kk];
            float a2 = Qs[(ty * 4 + 2) * 256 + kc + kk];
            float a3 = Qs[(ty * 4 + 3) * 256 + kc + kk];
            #pragma unroll
            for (int jj = 0; jj < 9; jj++) {
                float kv = Ks[(tx * 9 + jj) * KST + kk];
                acc[0][jj] = fmaf(a0, kv, acc[0][jj]);
                acc[1][jj] = fmaf(a1, kv, acc[1][jj]);
                acc[2][jj] = fmaf(a2, kv, acc[2][jj]);
                acc[3][jj] = fmaf(a3, kv, acc[3][jj]);
            }
        }
    }
    __syncthreads();
    #pragma unroll
    for (int r = 0; r < 4; r++)
        #pragma unroll
        for (int jj = 0; jj < 9; jj++)
            Ssm[(ty * 4 + r) * SST + tx * 9 + jj] = acc[r][jj];
    __syncthreads();

    // softmax: warp ty owns rows ty*4..ty*4+3; window j in [i, i+256]
    for (int r = 0; r < 4; r++) {
        int i = ty * 4 + r;
        float m = -1e30f;
        for (int j = i + tx; j <= i + 256; j += 32)
            m = fmaxf(m, Ssm[i * SST + j]);
        #pragma unroll
        for (int o = 16; o > 0; o >>= 1)
            m = fmaxf(m, __shfl_xor_sync(0xffffffffu, m, o));
        float l = 0.f;
        for (int j = i + tx; j <= i + 256; j += 32) {
            float e = __expf(Ssm[i * SST + j] - m);
            Ssm[i * SST + j] = e;
            l += e;
        }
        #pragma unroll
        for (int o = 16; o > 0; o >>= 1)
            l += __shfl_xor_sync(0xffffffffu, l, o);
        float inv = 1.f / l;
        for (int j = tx; j < KR; j += 32) {
            float pv = Ssm[i * SST + j];
            pv = (j >= i && j <= i + 256) ? pv * inv : 0.f;
            Ssm[i * SST + j] = pv;
        }
    }
    __syncthreads();

    // Phase 2: O = P @ Vpad, two column chunks of 128
    for (int ec = 0; ec < 256; ec += 128) {
        #pragma unroll
        for (int p = 0; p < 36; p++) {
            int idx4 = tid + p * 256;
            int row  = idx4 >> 5;          // 0..287
            int c4   = (idx4 & 31) * 4;    // 0..124
            int g    = s0 - 128 + row;
            float4 v = make_float4(0.f, 0.f, 0.f, 0.f);
            if ((unsigned)g < S_LEN)
                v = *(const float4*)&vg[(size_t)g * 256 + ec + c4];
            *(float4*)&Vs[row * VST + c4] = v;
        }
        __syncthreads();

        float4 o0 = make_float4(0.f, 0.f, 0.f, 0.f);
        float4 o1 = o0, o2 = o0, o3 = o0;
        #pragma unroll 4
        for (int j = 0; j < KR; j++) {
            float4 vv = *(const float4*)&Vs[j * VST + tx * 4];
            float p0 = Ssm[(ty * 4 + 0) * SST + j];
            float p1 = Ssm[(ty * 4 + 1) * SST + j];
            float p2 = Ssm[(ty * 4 + 2) * SST + j];
            float p3 = Ssm[(ty * 4 + 3) * SST + j];
            o0.x = fmaf(p0, vv.x, o0.x); o0.y = fmaf(p0, vv.y, o0.y);
            o0.z = fmaf(p0, vv.z, o0.z); o0.w = fmaf(p0, vv.w, o0.w);
            o1.x = fmaf(p1, vv.x, o1.x); o1.y = fmaf(p1, vv.y, o1.y);
            o1.z = fmaf(p1, vv.z, o1.z); o1.w = fmaf(p1, vv.w, o1.w);
            o2.x = fmaf(p2, vv.x, o2.x); o2.y = fmaf(p2, vv.y, o2.y);
            o2.z = fmaf(p2, vv.z, o2.z); o2.w = fmaf(p2, vv.w, o2.w);
            o3.x = fmaf(p3, vv.x, o3.x); o3.y = fmaf(p3, vv.y, o3.y);
            o3.z = fmaf(p3, vv.z, o3.z); o3.w = fmaf(p3, vv.w, o3.w);
        }
        size_t base = ((size_t)b * S_LEN + s0 + ty * 4) * 256 + ec + tx * 4;
        *(float4*)&out[base + 0 * 256] = o0;
        *(float4*)&out[base + 1 * 256] = o1;
        *(float4*)&out[base + 2 * 256] = o2;
        *(float4*)&out[base + 3 * 256] = o3;
        __syncthreads();   // Vs reused next chunk
    }
}

// ---------------------------------------------------------------------------
extern "C" void kernel_launch(void* const* d_in, const int* in_sizes, int n_in,
                              void* d_out, int out_size)
{
    const float* x  = (const float*)d_in[0];
    const float* Wq = (const float*)d_in[1];
    const float* bq = (const float*)d_in[2];
    const float* Wk = (const float*)d_in[3];
    const float* bk = (const float*)d_in[4];
    const float* Wv = (const float*)d_in[5];
    const float* bv = (const float*)d_in[6];
    float* out = (float*)d_out;

    const int smem_bytes = (TQ * SST + KR * VST) * sizeof(float);  // 189440
    cudaFuncSetAttribute(attn_kernel,
                         cudaFuncAttributeMaxDynamicSharedMemorySize, smem_bytes);

    qkv_kernel<<<dim3(32, 2, 3), 256>>>(x, Wq, bq, Wk, bk, Wv, bv);
    attn_kernel<<<dim3(S_LEN / TQ, B_SZ), 256, smem_bytes>>>(out);
}

// round 4
// speedup vs baseline: 1.3023x; 1.3023x over previous
#include <cuda_runtime.h>
#include <cuda_bf16.h>
#include <cstdint>

#define B_SZ  2
#define S_LEN 2048
#define E_DIM 256
#define TQ    32          // q rows per attention block
#define KR    288         // k/v rows per tile: TQ + 2*128
#define SST   292         // Ssm row stride (floats)
#define KST   33          // Ks row stride
#define VST   132         // Vs row stride

// scratch for q,k,v (no cudaMalloc allowed)
__device__ float g_q[B_SZ * S_LEN * E_DIM];
__device__ float g_k[B_SZ * S_LEN * E_DIM];
__device__ float g_v[B_SZ * S_LEN * E_DIM];

// ---------------------------------------------------------------------------
// mma.sync helpers (sm_80+ path; valid on bare sm_100 target)
// ---------------------------------------------------------------------------
__device__ __forceinline__ uint32_t smem_u32(const void* p) {
    uint32_t a;
    asm("{ .reg .u64 t; cvta.to.shared.u64 t, %1; cvt.u32.u64 %0, t; }"
        : "=r"(a) : "l"(p));
    return a;
}

__device__ __forceinline__ void ldsm_x4(uint32_t& r0, uint32_t& r1,
                                        uint32_t& r2, uint32_t& r3, uint32_t a) {
    asm volatile("ldmatrix.sync.aligned.m8n8.x4.shared.b16 {%0,%1,%2,%3}, [%4];"
                 : "=r"(r0), "=r"(r1), "=r"(r2), "=r"(r3) : "r"(a));
}

__device__ __forceinline__ void ldsm_x2(uint32_t& r0, uint32_t& r1, uint32_t a) {
    asm volatile("ldmatrix.sync.aligned.m8n8.x2.shared.b16 {%0,%1}, [%2];"
                 : "=r"(r0), "=r"(r1) : "r"(a));
}

__device__ __forceinline__ void mma_bf16(float* d, const uint32_t* a,
                                         const uint32_t* b) {
    asm volatile(
        "mma.sync.aligned.m16n8k16.row.col.f32.bf16.bf16.f32 "
        "{%0,%1,%2,%3}, {%4,%5,%6,%7}, {%8,%9}, {%0,%1,%2,%3};"
        : "+f"(d[0]), "+f"(d[1]), "+f"(d[2]), "+f"(d[3])
        : "r"(a[0]), "r"(a[1]), "r"(a[2]), "r"(a[3]), "r"(b[0]), "r"(b[1]));
}

// split x into bf16 hi + lo (combined ~17 mantissa bits)
__device__ __forceinline__ void bf16_split(float x, __nv_bfloat16& hi,
                                           __nv_bfloat16& lo) {
    hi = __float2bfloat16_rn(x);
    lo = __float2bfloat16_rn(x - __bfloat162float(hi));
}

// ---------------------------------------------------------------------------
// Kernel 1: QKV projection, bf16-split mma.sync.
// C = X @ W^T + b, CTA tile M=128 N=128 K=256 (BK=32).
// grid (32, 2, 3): x->M tile, y->N half, z->{q,k,v}. 256 threads, 8 warps 2x4.
// ---------------------------------------------------------------------------
#define QST 40   // smem halfword stride: 80B rows -> 16B-aligned ldmatrix rows,
                 // r*80 mod 128 all-distinct -> conflict-free

__global__ __launch_bounds__(256) void qkv_tc_kernel(
    const float* __restrict__ x,
    const float* __restrict__ Wq, const float* __restrict__ bq,
    const float* __restrict__ Wk, const float* __restrict__ bk,
    const float* __restrict__ Wv, const float* __restrict__ bv)
{
    __shared__ __align__(16) __nv_bfloat16 sAhi[128 * QST];
    __shared__ __align__(16) __nv_bfloat16 sAlo[128 * QST];
    __shared__ __align__(16) __nv_bfloat16 sBhi[128 * QST];
    __shared__ __align__(16) __nv_bfloat16 sBlo[128 * QST];

    const int z = blockIdx.z;
    const float* __restrict__ W    = (z == 0) ? Wq : (z == 1) ? Wk : Wv;
    const float* __restrict__ bias = (z == 0) ? bq : (z == 1) ? bk : bv;
    float* __restrict__ C          = (z == 0) ? g_q : (z == 1) ? g_k : g_v;

    const int m0 = blockIdx.x * 128;
    const int n0 = blockIdx.y * 128;
    const int tid  = threadIdx.x;
    const int wid  = tid >> 5;
    const int lane = tid & 31;
    const int wm   = wid >> 2;       // 0..1 -> 64-row half
    const int wn   = wid & 3;        // 0..3 -> 32-col quarter

    const uint32_t uAhi = smem_u32(sAhi);
    const uint32_t uAlo = smem_u32(sAlo);
    const uint32_t uBhi = smem_u32(sBhi);
    const uint32_t uBlo = smem_u32(sBlo);

    float acc[4][4][4];
    #pragma unroll
    for (int i = 0; i < 4; i++)
        #pragma unroll
        for (int j = 0; j < 4; j++)
            #pragma unroll
            for (int e = 0; e < 4; e++) acc[i][j][e] = 0.f;

    // precomputed ldmatrix lane addressing
    const int aRow = (lane & 15);                 // within 16-row frag
    const int aCol = (lane >> 4) * 8;             // 0 or 8
    const int l15  = lane & 15;
    const int bRow = (l15 & 7);
    const int bCol = (l15 >> 3) * 8;

    for (int c = 0; c < 8; c++) {
        const int kc = c * 32;
        __syncthreads();
        #pragma unroll
        for (int p = 0; p < 4; p++) {
            int i4  = tid + p * 256;
            int row = i4 >> 3;           // 0..127
            int c4  = (i4 & 7) * 4;      // 0..28
            float4 v = *(const float4*)&x[(size_t)(m0 + row) * 256 + kc + c4];
            __nv_bfloat16 h0, l0, h1, l1, h2, l2, h3, l3;
            bf16_split(v.x, h0, l0); bf16_split(v.y, h1, l1);
            bf16_split(v.z, h2, l2); bf16_split(v.w, h3, l3);
            __nv_bfloat162* ph = (__nv_bfloat162*)&sAhi[row * QST + c4];
            __nv_bfloat162* pl = (__nv_bfloat162*)&sAlo[row * QST + c4];
            ph[0] = __nv_bfloat162(h0, h1); ph[1] = __nv_bfloat162(h2, h3);
            pl[0] = __nv_bfloat162(l0, l1); pl[1] = __nv_bfloat162(l2, l3);

            v = *(const float4*)&W[(size_t)(n0 + row) * 256 + kc + c4];
            bf16_split(v.x, h0, l0); bf16_split(v.y, h1, l1);
            bf16_split(v.z, h2, l2); bf16_split(v.w, h3, l3);
            ph = (__nv_bfloat162*)&sBhi[row * QST + c4];
            pl = (__nv_bfloat162*)&sBlo[row * QST + c4];
            ph[0] = __nv_bfloat162(h0, h1); ph[1] = __nv_bfloat162(h2, h3);
            pl[0] = __nv_bfloat162(l0, l1); pl[1] = __nv_bfloat162(l2, l3);
        }
        __syncthreads();

        #pragma unroll
        for (int kk = 0; kk < 32; kk += 16) {
            uint32_t ah[4][4], al[4][4], bh[4][2], bl[4][2];
            #pragma unroll
            for (int mi = 0; mi < 4; mi++) {
                uint32_t off = (uint32_t)((wm * 64 + mi * 16 + aRow) * QST +
                                          kk + aCol) * 2;
                ldsm_x4(ah[mi][0], ah[mi][1], ah[mi][2], ah[mi][3], uAhi + off);
                ldsm_x4(al[mi][0], al[mi][1], al[mi][2], al[mi][3], uAlo + off);
            }
            #pragma unroll
            for (int nj = 0; nj < 4; nj++) {
                uint32_t off = (uint32_t)((wn * 32 + nj * 8 + bRow) * QST +
                                          kk + bCol) * 2;
                ldsm_x2(bh[nj][0], bh[nj][1], uBhi + off);
                ldsm_x2(bl[nj][0], bl[nj][1], uBlo + off);
            }
            #pragma unroll
            for (int mi = 0; mi < 4; mi++)
                #pragma unroll
                for (int nj = 0; nj < 4; nj++) {
                    mma_bf16(acc[mi][nj], ah[mi], bh[nj]);
                    mma_bf16(acc[mi][nj], ah[mi], bl[nj]);
                    mma_bf16(acc[mi][nj], al[mi], bh[nj]);
                }
        }
    }

    // epilogue: D fragment -> rows (l>>2, l>>2+8), cols (l&3)*2 + {0,1}
    #pragma unroll
    for (int mi = 0; mi < 4; mi++) {
        int r0 = m0 + wm * 64 + mi * 16 + (lane >> 2);
        #pragma unroll
        for (int nj = 0; nj < 4; nj++) {
            int col = n0 + wn * 32 + nj * 8 + (lane & 3) * 2;
            float2 bv2 = *(const float2*)&bias[col];
            float2 o;
            o.x = acc[mi][nj][0] + bv2.x;
            o.y = acc[mi][nj][1] + bv2.y;
            *(float2*)&C[(size_t)r0 * 256 + col] = o;
            o.x = acc[mi][nj][2] + bv2.x;
            o.y = acc[mi][nj][3] + bv2.y;
            *(float2*)&C[(size_t)(r0 + 8) * 256 + col] = o;
        }
    }
}

// ---------------------------------------------------------------------------
// Kernel 2: banded attention, fp32, 512 threads (16 warps).
// Block = 32 q rows of one batch; K-range = 288 zero-padded rows.
// ---------------------------------------------------------------------------
__global__ __launch_bounds__(512) void attn_kernel(float* __restrict__ out)
{
    extern __shared__ float sm[];
    float* Ssm = sm;                       // TQ * SST = 9344 floats
    float* Qs  = sm + TQ * SST;            // 32*256 = 8192 floats
    float* Ks  = Qs + TQ * E_DIM;          // 288*33 = 9504 floats
    float* Vs  = sm + TQ * SST;            // 288*132 = 38016 (reuses Qs+Ks)

    const int b   = blockIdx.y;
    const int s0  = blockIdx.x * TQ;
    const int tid = threadIdx.x;
    const int w   = tid >> 5;              // warp 0..15
    const int tx  = tid & 31;

    const float* __restrict__ qg = g_q + (size_t)b * S_LEN * E_DIM;
    const float* __restrict__ kg = g_k + (size_t)b * S_LEN * E_DIM;
    const float* __restrict__ vg = g_v + (size_t)b * S_LEN * E_DIM;

    // load Q tile [32][256]
    #pragma unroll
    for (int p = 0; p < 4; p++) {
        int idx4 = tid + p * 512;
        int row  = idx4 >> 6;
        int c4   = (idx4 & 63) * 4;
        *(float4*)&Qs[row * 256 + c4] =
            *(const float4*)&qg[(size_t)(s0 + row) * 256 + c4];
    }

    // Phase 1: energy GEMM. warp w -> 2 q rows, lane -> 9 cols
    float acc[2][9];
    #pragma unroll
    for (int r = 0; r < 2; r++)
        #pragma unroll
        for (int j = 0; j < 9; j++) acc[r][j] = 0.f;

    for (int kc = 0; kc < 256; kc += 32) {
        __syncthreads();
        #pragma unroll
        for (int p = 0; p < 5; p++) {
            int idx4 = tid + p * 512;
            if (idx4 < 2304) {
                int row = idx4 >> 3;           // 0..287
                int c4  = (idx4 & 7) * 4;
                int g   = s0 - 128 + row;
                float4 v = make_float4(0.f, 0.f, 0.f, 0.f);
                if ((unsigned)g < S_LEN)
                    v = *(const float4*)&kg[(size_t)g * 256 + kc + c4];
                Ks[row * KST + c4 + 0] = v.x;
                Ks[row * KST + c4 + 1] = v.y;
                Ks[row * KST + c4 + 2] = v.z;
                Ks[row * KST + c4 + 3] = v.w;
            }
        }
        __syncthreads();
        #pragma unroll
        for (int kk = 0; kk < 32; kk++) {
            float a0 = Qs[(w * 2 + 0) * 256 + kc + kk];
            float a1 = Qs[(w * 2 + 1) * 256 + kc + kk];
            #pragma unroll
            for (int jj = 0; jj < 9; jj++) {
                float kv = Ks[(tx * 9 + jj) * KST + kk];
                acc[0][jj] = fmaf(a0, kv, acc[0][jj]);
                acc[1][jj] = fmaf(a1, kv, acc[1][jj]);
            }
        }
    }
    __syncthreads();
    #pragma unroll
    for (int r = 0; r < 2; r++)
        #pragma unroll
        for (int jj = 0; jj < 9; jj++)
            Ssm[(w * 2 + r) * SST + tx * 9 + jj] = acc[r][jj];
    __syncthreads();

    // softmax: warp w owns rows w*2, w*2+1; window j in [i, i+256]
    for (int r = 0; r < 2; r++) {
        int i = w * 2 + r;
        float m = -1e30f;
        for (int j = i + tx; j <= i + 256; j += 32)
            m = fmaxf(m, Ssm[i * SST + j]);
        #pragma unroll
        for (int o = 16; o > 0; o >>= 1)
            m = fmaxf(m, __shfl_xor_sync(0xffffffffu, m, o));
        float l = 0.f;
        for (int j = i + tx; j <= i + 256; j += 32) {
            float e = __expf(Ssm[i * SST + j] - m);
            Ssm[i * SST + j] = e;
            l += e;
        }
        #pragma unroll
        for (int o = 16; o > 0; o >>= 1)
            l += __shfl_xor_sync(0xffffffffu, l, o);
        float inv = 1.f / l;
        for (int j = tx; j < KR; j += 32) {
            float pv = Ssm[i * SST + j];
            pv = (j >= i && j <= i + 256) ? pv * inv : 0.f;
            Ssm[i * SST + j] = pv;
        }
    }
    __syncthreads();

    // Phase 2: O = P @ Vpad, two column chunks of 128
    for (int ec = 0; ec < 256; ec += 128) {
        #pragma unroll
        for (int p = 0; p < 18; p++) {
            int idx4 = tid + p * 512;          // 9216 float4
            int row  = idx4 >> 5;              // 0..287
            int c4   = (idx4 & 31) * 4;        // 0..124
            int g    = s0 - 128 + row;
            float4 v = make_float4(0.f, 0.f, 0.f, 0.f);
            if ((unsigned)g < S_LEN)
                v = *(const float4*)&vg[(size_t)g * 256 + ec + c4];
            *(float4*)&Vs[row * VST + c4] = v;
        }
        __syncthreads();

        float4 o0 = make_float4(0.f, 0.f, 0.f, 0.f);
        float4 o1 = o0;
        #pragma unroll 4
        for (int j = 0; j < KR; j++) {
            float4 vv = *(const float4*)&Vs[j * VST + tx * 4];
            float p0 = Ssm[(w * 2 + 0) * SST + j];
            float p1 = Ssm[(w * 2 + 1) * SST + j];
            o0.x = fmaf(p0, vv.x, o0.x); o0.y = fmaf(p0, vv.y, o0.y);
            o0.z = fmaf(p0, vv.z, o0.z); o0.w = fmaf(p0, vv.w, o0.w);
            o1.x = fmaf(p1, vv.x, o1.x); o1.y = fmaf(p1, vv.y, o1.y);
            o1.z = fmaf(p1, vv.z, o1.z); o1.w = fmaf(p1, vv.w, o1.w);
        }
        size_t base = ((size_t)b * S_LEN + s0 + w * 2) * 256 + ec + tx * 4;
        *(float4*)&out[base + 0 * 256] = o0;
        *(float4*)&out[base + 1 * 256] = o1;
        __syncthreads();   // Vs reused next chunk
    }
}

// ---------------------------------------------------------------------------
extern "C" void kernel_launch(void* const* d_in, const int* in_sizes, int n_in,
                              void* d_out, int out_size)
{
    const float* x  = (const float*)d_in[0];
    const float* Wq = (const float*)d_in[1];
    const float* bq = (const float*)d_in[2];
    const float* Wk = (const float*)d_in[3];
    const float* bk = (const float*)d_in[4];
    const float* Wv = (const float*)d_in[5];
    const float* bv = (const float*)d_in[6];
    float* out = (float*)d_out;

    const int attn_smem = (TQ * SST + KR * VST) * sizeof(float);     // 189440
    cudaFuncSetAttribute(attn_kernel,
                         cudaFuncAttributeMaxDynamicSharedMemorySize, attn_smem);

    qkv_tc_kernel<<<dim3(32, 2, 3), 256>>>(x, Wq, bq, Wk, bk, Wv, bv);
    attn_kernel<<<dim3(S_LEN / TQ, B_SZ), 512, attn_smem>>>(out);
}

// round 6
// speedup vs baseline: 1.9289x; 1.4811x over previous
#include <cuda_runtime.h>
#include <cuda_bf16.h>
#include <cstdint>

#define B_SZ  2
#define S_LEN 2048
#define E_DIM 256
#define TQ    32          // q rows per attention block
#define KR    288         // k rows per block window
#define SST   292         // Ssm f32 row stride
#define QSA   264         // Q smem halfword stride (528B rows)
#define KVT   72          // K/V chunk halfword stride (144B rows)
#define PST   296         // P smem halfword stride (592B rows)

// bf16 hi/lo scratch for q,k,v (no cudaMalloc allowed)
__device__ __nv_bfloat16 g_qh[B_SZ * S_LEN * E_DIM];
__device__ __nv_bfloat16 g_ql[B_SZ * S_LEN * E_DIM];
__device__ __nv_bfloat16 g_kh[B_SZ * S_LEN * E_DIM];
__device__ __nv_bfloat16 g_kl[B_SZ * S_LEN * E_DIM];
__device__ __nv_bfloat16 g_vh[B_SZ * S_LEN * E_DIM];
__device__ __nv_bfloat16 g_vl[B_SZ * S_LEN * E_DIM];

// ---------------------------------------------------------------------------
// mma.sync helpers
// ---------------------------------------------------------------------------
__device__ __forceinline__ uint32_t smem_u32(const void* p) {
    uint32_t a;
    asm("{ .reg .u64 t; cvta.to.shared.u64 t, %1; cvt.u32.u64 %0, t; }"
        : "=r"(a) : "l"(p));
    return a;
}

__device__ __forceinline__ void ldsm_x4(uint32_t& r0, uint32_t& r1,
                                        uint32_t& r2, uint32_t& r3, uint32_t a) {
    asm volatile("ldmatrix.sync.aligned.m8n8.x4.shared.b16 {%0,%1,%2,%3}, [%4];"
                 : "=r"(r0), "=r"(r1), "=r"(r2), "=r"(r3) : "r"(a));
}

__device__ __forceinline__ void ldsm_x4_t(uint32_t& r0, uint32_t& r1,
                                          uint32_t& r2, uint32_t& r3, uint32_t a) {
    asm volatile("ldmatrix.sync.aligned.m8n8.x4.trans.shared.b16 {%0,%1,%2,%3}, [%4];"
                 : "=r"(r0), "=r"(r1), "=r"(r2), "=r"(r3) : "r"(a));
}

__device__ __forceinline__ void ldsm_x2(uint32_t& r0, uint32_t& r1, uint32_t a) {
    asm volatile("ldmatrix.sync.aligned.m8n8.x2.shared.b16 {%0,%1}, [%2];"
                 : "=r"(r0), "=r"(r1) : "r"(a));
}

__device__ __forceinline__ void mma_bf16(float* d, const uint32_t* a,
                                         const uint32_t* b) {
    asm volatile(
        "mma.sync.aligned.m16n8k16.row.col.f32.bf16.bf16.f32 "
        "{%0,%1,%2,%3}, {%4,%5,%6,%7}, {%8,%9}, {%0,%1,%2,%3};"
        : "+f"(d[0]), "+f"(d[1]), "+f"(d[2]), "+f"(d[3])
        : "r"(a[0]), "r"(a[1]), "r"(a[2]), "r"(a[3]), "r"(b[0]), "r"(b[1]));
}

__device__ __forceinline__ void bf16_split(float x, __nv_bfloat16& hi,
                                           __nv_bfloat16& lo) {
    hi = __float2bfloat16_rn(x);
    lo = __float2bfloat16_rn(x - __bfloat162float(hi));
}

// ---------------------------------------------------------------------------
// Kernel 1: QKV projection, bf16-split mma.sync; emits bf16 hi/lo q,k,v.
// C = X @ W^T + b, CTA tile M=128 N=128 K=256 (BK=32).
// grid (32, 2, 3), 256 threads, 8 warps 2x4.
// ---------------------------------------------------------------------------
#define QST 40   // 80B rows: 16B-aligned, conflict-free

__global__ __launch_bounds__(256) void qkv_tc_kernel(
    const float* __restrict__ x,
    const float* __restrict__ Wq, const float* __restrict__ bq,
    const float* __restrict__ Wk, const float* __restrict__ bk,
    const float* __restrict__ Wv, const float* __restrict__ bv)
{
    __shared__ __align__(16) __nv_bfloat16 sAhi[128 * QST];
    __shared__ __align__(16) __nv_bfloat16 sAlo[128 * QST];
    __shared__ __align__(16) __nv_bfloat16 sBhi[128 * QST];
    __shared__ __align__(16) __nv_bfloat16 sBlo[128 * QST];

    const int z = blockIdx.z;
    const float* __restrict__ W    = (z == 0) ? Wq : (z == 1) ? Wk : Wv;
    const float* __restrict__ bias = (z == 0) ? bq : (z == 1) ? bk : bv;
    __nv_bfloat16* __restrict__ Ch = (z == 0) ? g_qh : (z == 1) ? g_kh : g_vh;
    __nv_bfloat16* __restrict__ Cl = (z == 0) ? g_ql : (z == 1) ? g_kl : g_vl;

    const int m0 = blockIdx.x * 128;
    const int n0 = blockIdx.y * 128;
    const int tid  = threadIdx.x;
    const int wid  = tid >> 5;
    const int lane = tid & 31;
    const int wm   = wid >> 2;
    const int wn   = wid & 3;

    const uint32_t uAhi = smem_u32(sAhi);
    const uint32_t uAlo = smem_u32(sAlo);
    const uint32_t uBhi = smem_u32(sBhi);
    const uint32_t uBlo = smem_u32(sBlo);

    float acc[4][4][4];
    #pragma unroll
    for (int i = 0; i < 4; i++)
        #pragma unroll
        for (int j = 0; j < 4; j++)
            #pragma unroll
            for (int e = 0; e < 4; e++) acc[i][j][e] = 0.f;

    const int aRow = (lane & 15);
    const int aCol = (lane >> 4) * 8;
    const int l15  = lane & 15;
    const int bRow = (l15 & 7);
    const int bCol = (l15 >> 3) * 8;

    for (int c = 0; c < 8; c++) {
        const int kc = c * 32;
        __syncthreads();
        #pragma unroll
        for (int p = 0; p < 4; p++) {
            int i4  = tid + p * 256;
            int row = i4 >> 3;
            int c4  = (i4 & 7) * 4;
            float4 v = *(const float4*)&x[(size_t)(m0 + row) * 256 + kc + c4];
            __nv_bfloat16 h0, l0, h1, l1, h2, l2, h3, l3;
            bf16_split(v.x, h0, l0); bf16_split(v.y, h1, l1);
            bf16_split(v.z, h2, l2); bf16_split(v.w, h3, l3);
            __nv_bfloat162* ph = (__nv_bfloat162*)&sAhi[row * QST + c4];
            __nv_bfloat162* pl = (__nv_bfloat162*)&sAlo[row * QST + c4];
            ph[0] = __nv_bfloat162(h0, h1); ph[1] = __nv_bfloat162(h2, h3);
            pl[0] = __nv_bfloat162(l0, l1); pl[1] = __nv_bfloat162(l2, l3);

            v = *(const float4*)&W[(size_t)(n0 + row) * 256 + kc + c4];
            bf16_split(v.x, h0, l0); bf16_split(v.y, h1, l1);
            bf16_split(v.z, h2, l2); bf16_split(v.w, h3, l3);
            ph = (__nv_bfloat162*)&sBhi[row * QST + c4];
            pl = (__nv_bfloat162*)&sBlo[row * QST + c4];
            ph[0] = __nv_bfloat162(h0, h1); ph[1] = __nv_bfloat162(h2, h3);
            pl[0] = __nv_bfloat162(l0, l1); pl[1] = __nv_bfloat162(l2, l3);
        }
        __syncthreads();

        #pragma unroll
        for (int kk = 0; kk < 32; kk += 16) {
            uint32_t ah[4][4], al[4][4], bh[4][2], bl[4][2];
            #pragma unroll
            for (int mi = 0; mi < 4; mi++) {
                uint32_t off = (uint32_t)((wm * 64 + mi * 16 + aRow) * QST +
                                          kk + aCol) * 2;
                ldsm_x4(ah[mi][0], ah[mi][1], ah[mi][2], ah[mi][3], uAhi + off);
                ldsm_x4(al[mi][0], al[mi][1], al[mi][2], al[mi][3], uAlo + off);
            }
            #pragma unroll
            for (int nj = 0; nj < 4; nj++) {
                uint32_t off = (uint32_t)((wn * 32 + nj * 8 + bRow) * QST +
                                          kk + bCol) * 2;
                ldsm_x2(bh[nj][0], bh[nj][1], uBhi + off);
                ldsm_x2(bl[nj][0], bl[nj][1], uBlo + off);
            }
            #pragma unroll
            for (int mi = 0; mi < 4; mi++)
                #pragma unroll
                for (int nj = 0; nj < 4; nj++) {
                    mma_bf16(acc[mi][nj], ah[mi], bh[nj]);
                    mma_bf16(acc[mi][nj], ah[mi], bl[nj]);
                    mma_bf16(acc[mi][nj], al[mi], bh[nj]);
                }
        }
    }

    // epilogue: add bias, split to bf16 hi/lo, store
    #pragma unroll
    for (int mi = 0; mi < 4; mi++) {
        int r0 = m0 + wm * 64 + mi * 16 + (lane >> 2);
        #pragma unroll
        for (int nj = 0; nj < 4; nj++) {
            int col = n0 + wn * 32 + nj * 8 + (lane & 3) * 2;
            float2 bv2 = *(const float2*)&bias[col];
            #pragma unroll
            for (int h = 0; h < 2; h++) {
                int row = r0 + h * 8;
                float cx = acc[mi][nj][h * 2 + 0] + bv2.x;
                float cy = acc[mi][nj][h * 2 + 1] + bv2.y;
                __nv_bfloat16 hx, lx, hy, ly;
                bf16_split(cx, hx, lx);
                bf16_split(cy, hy, ly);
                *(__nv_bfloat162*)&Ch[(size_t)row * 256 + col] = __nv_bfloat162(hx, hy);
                *(__nv_bfloat162*)&Cl[(size_t)row * 256 + col] = __nv_bfloat162(lx, ly);
            }
        }
    }
}

// ---------------------------------------------------------------------------
// Kernel 2: banded attention, fully tensor-core (bf16-split mma.sync).
// Block = 32 q rows of one batch, 256 threads, 8 warps (2 m x 4 n).
// smem layout (dynamic, bytes):
//   Ssm  f32 [32][292]          @ 0       (37376)
//   Qh/Ql bf16 [32][264]        @ 37376 / 54272  (16896 each)
//   Ph/Pl bf16 [32][296]        @ 71168 / 90112  (18944 each)
//   Kh/Kl (reused Vh/Vl) [288][72] @ 109056 / 150528 (41472 each)
// total 192000
// ---------------------------------------------------------------------------
#define OFF_QH 37376
#define OFF_QL 54272
#define OFF_PH 71168
#define OFF_PL 90112
#define OFF_KH 109056
#define OFF_KL 150528
#define ATTN_SMEM 192000

__global__ __launch_bounds__(256) void attn_tc_kernel(float* __restrict__ out)
{
    extern __shared__ char smem[];
    float* Ssm = (float*)smem;
    __nv_bfloat16* Qh = (__nv_bfloat16*)(smem + OFF_QH);
    __nv_bfloat16* Ql = (__nv_bfloat16*)(smem + OFF_QL);
    __nv_bfloat16* Ph = (__nv_bfloat16*)(smem + OFF_PH);
    __nv_bfloat16* Pl = (__nv_bfloat16*)(smem + OFF_PL);
    __nv_bfloat16* Kh = (__nv_bfloat16*)(smem + OFF_KH);  // also V
    __nv_bfloat16* Kl = (__nv_bfloat16*)(smem + OFF_KL);

    const uint32_t uQh = smem_u32(Qh), uQl = smem_u32(Ql);
    const uint32_t uPh = smem_u32(Ph), uPl = smem_u32(Pl);
    const uint32_t uKh = smem_u32(Kh), uKl = smem_u32(Kl);

    const int b   = blockIdx.y;
    const int s0  = blockIdx.x * TQ;
    const int tid = threadIdx.x;
    const int wid = tid >> 5;
    const int lane = tid & 31;
    const int wm  = wid >> 2;        // 0..1 -> 16-row half
    const int wn  = wid & 3;         // 0..3

    const size_t boff = (size_t)b * S_LEN * E_DIM;
    const __nv_bfloat16* __restrict__ qh = g_qh + boff;
    const __nv_bfloat16* __restrict__ ql = g_ql + boff;
    const __nv_bfloat16* __restrict__ kh = g_kh + boff;
    const __nv_bfloat16* __restrict__ kl = g_kl + boff;
    const __nv_bfloat16* __restrict__ vh = g_vh + boff;
    const __nv_bfloat16* __restrict__ vl = g_vl + boff;

    // ldmatrix lane addressing
    const int aRow = lane & 15;
    const int aCol = (lane >> 4) * 8;
    const int bRowE = (lane & 7) + ((lane >> 4) << 3);  // energy B (x4, 2 n-tiles)
    const int bColE = ((lane >> 3) & 1) * 8;
    const int vRow = lane & 15;                          // PV B trans (x4)
    const int vCol = (lane >> 4) * 8;

    // ---- load Q tile [32][256] hi/lo ----
    #pragma unroll
    for (int p = 0; p < 4; p++) {
        int idx = tid + p * 256;            // 1024
        int row = idx >> 5;
        int c8  = (idx & 31) * 8;
        *(uint4*)&Qh[row * QSA + c8] = *(const uint4*)&qh[(size_t)(s0 + row) * 256 + c8];
        *(uint4*)&Ql[row * QSA + c8] = *(const uint4*)&ql[(size_t)(s0 + row) * 256 + c8];
    }

    // ---- Phase 1: energy S[32][288] = Q @ K^T ----
    float acc[9][4];
    #pragma unroll
    for (int t = 0; t < 9; t++)
        #pragma unroll
        for (int e = 0; e < 4; e++) acc[t][e] = 0.f;

    for (int kc = 0; kc < 256; kc += 64) {
        __syncthreads();  // Q ready (1st) / prev MMA done with K smem
        #pragma unroll
        for (int p = 0; p < 9; p++) {
            int idx = tid + p * 256;       // 2304
            int row = idx >> 3;            // 0..287
            int c8  = (idx & 7) * 8;       // 0..56
            int g   = s0 - 128 + row;
            uint4 zh = make_uint4(0, 0, 0, 0), zl = zh;
            if ((unsigned)g < S_LEN) {
                zh = *(const uint4*)&kh[(size_t)g * 256 + kc + c8];
                zl = *(const uint4*)&kl[(size_t)g * 256 + kc + c8];
            }
            *(uint4*)&Kh[row * KVT + c8] = zh;
            *(uint4*)&Kl[row * KVT + c8] = zl;
        }
        __syncthreads();

        #pragma unroll
        for (int kk = 0; kk < 64; kk += 16) {
            uint32_t ah[4], al[4];
            {
                uint32_t off = (uint32_t)((wm * 16 + aRow) * QSA + kc + kk + aCol) * 2;
                ldsm_x4(ah[0], ah[1], ah[2], ah[3], uQh + off);
                ldsm_x4(al[0], al[1], al[2], al[3], uQl + off);
            }
            uint32_t bh[9][2], bl[9][2];
            #pragma unroll
            for (int t2 = 0; t2 < 4; t2++) {
                uint32_t off = (uint32_t)((wn * 72 + t2 * 16 + bRowE) * KVT +
                                          kk + bColE) * 2;
                ldsm_x4(bh[t2 * 2][0], bh[t2 * 2][1],
                        bh[t2 * 2 + 1][0], bh[t2 * 2 + 1][1], uKh + off);
                ldsm_x4(bl[t2 * 2][0], bl[t2 * 2][1],
                        bl[t2 * 2 + 1][0], bl[t2 * 2 + 1][1], uKl + off);
            }
            {
                uint32_t off = (uint32_t)((wn * 72 + 64 + (lane & 7)) * KVT +
                                          kk + bColE) * 2;
                ldsm_x2(bh[8][0], bh[8][1], uKh + off);
                ldsm_x2(bl[8][0], bl[8][1], uKl + off);
            }
            #pragma unroll
            for (int t = 0; t < 9; t++) {
                mma_bf16(acc[t], ah, bh[t]);
                mma_bf16(acc[t], ah, bl[t]);
                mma_bf16(acc[t], al, bh[t]);
            }
        }
    }

    // store energies to Ssm
    #pragma unroll
    for (int t = 0; t < 9; t++)
        #pragma unroll
        for (int h = 0; h < 2; h++) {
            int row = wm * 16 + (lane >> 2) + h * 8;
            int col = wn * 72 + t * 8 + (lane & 3) * 2;
            *(float2*)&Ssm[row * SST + col] =
                make_float2(acc[t][h * 2], acc[t][h * 2 + 1]);
        }
    __syncthreads();

    // ---- softmax: warp wid owns rows wid*4..wid*4+3; window [i, i+256] ----
    for (int r = 0; r < 4; r++) {
        int i = wid * 4 + r;
        float m = -1e30f;
        for (int j = i + lane; j <= i + 256; j += 32)
            m = fmaxf(m, Ssm[i * SST + j]);
        #pragma unroll
        for (int o = 16; o > 0; o >>= 1)
            m = fmaxf(m, __shfl_xor_sync(0xffffffffu, m, o));
        float l = 0.f;
        for (int j = i + lane; j <= i + 256; j += 32) {
            float e = __expf(Ssm[i * SST + j] - m);
            Ssm[i * SST + j] = e;
            l += e;
        }
        #pragma unroll
        for (int o = 16; o > 0; o >>= 1)
            l += __shfl_xor_sync(0xffffffffu, l, o);
        float inv = 1.f / l;
        for (int j = lane; j < KR; j += 32) {
            float pv = (j >= i && j <= i + 256) ? Ssm[i * SST + j] * inv : 0.f;
            __nv_bfloat16 hi, lo;
            bf16_split(pv, hi, lo);
            Ph[i * PST + j] = hi;
            Pl[i * PST + j] = lo;
        }
    }
    __syncthreads();

    // ---- Phase 2: O[32][256] = P[32][288] @ V[288][256] ----
    for (int ec = 0; ec < 256; ec += 64) {
        if (ec > 0) __syncthreads();
        #pragma unroll
        for (int p = 0; p < 9; p++) {
            int idx = tid + p * 256;
            int row = idx >> 3;
            int c8  = (idx & 7) * 8;
            int g   = s0 - 128 + row;
            uint4 zh = make_uint4(0, 0, 0, 0), zl = zh;
            if ((unsigned)g < S_LEN) {
                zh = *(const uint4*)&vh[(size_t)g * 256 + ec + c8];
                zl = *(const uint4*)&vl[(size_t)g * 256 + ec + c8];
            }
            *(uint4*)&Kh[row * KVT + c8] = zh;
            *(uint4*)&Kl[row * KVT + c8] = zl;
        }
        __syncthreads();

        float acc2[2][4];
        #pragma unroll
        for (int t = 0; t < 2; t++)
            #pragma unroll
            for (int e = 0; e < 4; e++) acc2[t][e] = 0.f;

        #pragma unroll 2
        for (int kk = 0; kk < KR; kk += 16) {
            uint32_t ah[4], al[4];
            {
                uint32_t off = (uint32_t)((wm * 16 + aRow) * PST + kk + aCol) * 2;
                ldsm_x4(ah[0], ah[1], ah[2], ah[3], uPh + off);
                ldsm_x4(al[0], al[1], al[2], al[3], uPl + off);
            }
            uint32_t bh[2][2], bl[2][2];
            {
                uint32_t off = (uint32_t)((kk + vRow) * KVT + wn * 16 + vCol) * 2;
                ldsm_x4_t(bh[0][0], bh[0][1], bh[1][0], bh[1][1], uKh + off);
                ldsm_x4_t(bl[0][0], bl[0][1], bl[1][0], bl[1][1], uKl + off);
            }
            #pragma unroll
            for (int t = 0; t < 2; t++) {
                mma_bf16(acc2[t], ah, bh[t]);
                mma_bf16(acc2[t], ah, bl[t]);
                mma_bf16(acc2[t], al, bh[t]);
            }
        }

        // epilogue: direct f32 stores
        #pragma unroll
        for (int t = 0; t < 2; t++)
            #pragma unroll
            for (int h = 0; h < 2; h++) {
                int row = s0 + wm * 16 + (lane >> 2) + h * 8;
                int col = ec + wn * 16 + t * 8 + (lane & 3) * 2;
                *(float2*)&out[((size_t)b * S_LEN + row) * 256 + col] =
                    make_float2(acc2[t][h * 2], acc2[t][h * 2 + 1]);
            }
    }
}

// ---------------------------------------------------------------------------
extern "C" void kernel_launch(void* const* d_in, const int* in_sizes, int n_in,
                              void* d_out, int out_size)
{
    const float* x  = (const float*)d_in[0];
    const float* Wq = (const float*)d_in[1];
    const float* bq = (const float*)d_in[2];
    const float* Wk = (const float*)d_in[3];
    const float* bk = (const float*)d_in[4];
    const float* Wv = (const float*)d_in[5];
    const float* bv = (const float*)d_in[6];
    float* out = (float*)d_out;

    cudaFuncSetAttribute(attn_tc_kernel,
                         cudaFuncAttributeMaxDynamicSharedMemorySize, ATTN_SMEM);

    qkv_tc_kernel<<<dim3(32, 2, 3), 256>>>(x, Wq, bq, Wk, bk, Wv, bv);
    attn_tc_kernel<<<dim3(S_LEN / TQ, B_SZ), 256, ATTN_SMEM>>>(out);
}